// round 13
// baseline (speedup 1.0000x reference)
#include <cuda_runtime.h>
#include <cuda_bf16.h>
#include <math.h>

// Problem constants
#define BB   2
#define NN   2048
#define RRoi 128
#define CINv 256
#define NSv  16
#define C1v  128
#define RADv 0.3f
#define EPSv 1e-5f
#define FEATS_SZ (BB*C1v*NN)          // 524288
#define GRIDN 148

// ---------------- scratch ----------------
__device__ int   g_idx[BB*NN*NSv];
__device__ float g_Gt[BB*NN*256];        // [b][n][o]
__device__ float g_hmax[BB*NN*256];      // [b][n][c]
__device__ float g_h2[BB*NN*C1v];        // [b][n][o]
__device__ float g_h3[BB*NN*C1v];        // [b][n][o]
__device__ float g_WxT[3*256];           // [k][o]
__device__ unsigned g_Wfh[256*128], g_Wfl[256*128];
__device__ unsigned g_W1h[128*128], g_W1l[128*128];
__device__ unsigned g_W2h[128*64],  g_W2l[128*64];
__device__ unsigned g_Fh[BB*NN*128],  g_Fl[BB*NN*128];
__device__ unsigned g_A1h[BB*NN*128], g_A1l[BB*NN*128];
__device__ unsigned g_A2h[BB*NN*64],  g_A2l[BB*NN*64];
__device__ int   g_roilst[BB*RRoi*NN];
__device__ int   g_roicnt[BB*RRoi];
__device__ float g_stats[1024];
// grid barrier state (self-resetting across launches)
__device__ int g_bcount = 0;
__device__ int g_bsense = 0;

// ---------------- helpers ----------------
__device__ __forceinline__ void barx(int id, int cnt) {
    asm volatile("bar.sync %0, %1;" :: "r"(id), "r"(cnt) : "memory");
}

__device__ __forceinline__ void gridbar() {
    __threadfence();
    __syncthreads();
    if (threadIdx.x == 0) {
        int s = *(volatile int*)&g_bsense;
        if (atomicAdd(&g_bcount, 1) == GRIDN - 1) {
            g_bcount = 0;
            __threadfence();
            *(volatile int*)&g_bsense = s ^ 1;
        } else {
            while (*(volatile int*)&g_bsense == s) __nanosleep(128);
        }
        __threadfence();
    }
    __syncthreads();
}

__device__ __forceinline__ unsigned pack_split(float x0, float x1, unsigned& lo) {
    __nv_bfloat16 h0 = __float2bfloat16(x0);
    __nv_bfloat16 h1 = __float2bfloat16(x1);
    __nv_bfloat16 l0 = __float2bfloat16(x0 - __bfloat162float(h0));
    __nv_bfloat16 l1 = __float2bfloat16(x1 - __bfloat162float(h1));
    lo = ((unsigned)__bfloat16_as_ushort(l1) << 16) | (unsigned)__bfloat16_as_ushort(l0);
    return ((unsigned)__bfloat16_as_ushort(h1) << 16) | (unsigned)__bfloat16_as_ushort(h0);
}

__device__ __forceinline__ void mma16816(float* d, const unsigned* a, const unsigned* b) {
    asm volatile(
        "mma.sync.aligned.m16n8k16.row.col.f32.bf16.bf16.f32 "
        "{%0,%1,%2,%3}, {%4,%5,%6,%7}, {%8,%9}, {%0,%1,%2,%3};"
        : "+f"(d[0]), "+f"(d[1]), "+f"(d[2]), "+f"(d[3])
        : "r"(a[0]), "r"(a[1]), "r"(a[2]), "r"(a[3]), "r"(b[0]), "r"(b[1]));
}

struct SmemGemm {
    unsigned wh[2][32][12], wl[2][32][12];
    unsigned ah[2][64][12], al[2][64][12];
    float outT[64][36];
};

// pure-MMA mainloop (R10-proven), named-barrier variant for 128-thread quarters
template<int KSTEPS>
__device__ __forceinline__ void gemm_mainloopP(
    SmemGemm& s,
    const unsigned* __restrict__ Wh, const unsigned* __restrict__ Wl,
    const unsigned* __restrict__ Ah, const unsigned* __restrict__ Al,
    int o0, size_t nbase, float (*d)[4], int tid, int barid)
{
    const int kw2 = KSTEPS * 8;
    int lane = tid & 31, warp = tid >> 5;
    int g = lane >> 2, t = lane & 3;
    int wn0 = warp * 16;
    int srw = tid >> 1;
    int sq = (tid & 1) * 4;
    if (tid < 64) {
        *(uint4*)&s.wh[0][srw][sq] = *(const uint4*)&Wh[(size_t)(o0 + srw) * kw2 + sq];
        *(uint4*)&s.wl[0][srw][sq] = *(const uint4*)&Wl[(size_t)(o0 + srw) * kw2 + sq];
    }
    *(uint4*)&s.ah[0][srw][sq] = *(const uint4*)&Ah[(nbase + srw) * kw2 + sq];
    *(uint4*)&s.al[0][srw][sq] = *(const uint4*)&Al[(nbase + srw) * kw2 + sq];
    barx(barid, 128);
    int buf = 0;
    #pragma unroll
    for (int ks = 0; ks < KSTEPS; ks++) {
        uint4 nwh, nwl, nah, nal;
        if (ks + 1 < KSTEPS) {
            int kw = (ks + 1) * 8 + sq;
            if (tid < 64) {
                nwh = *(const uint4*)&Wh[(size_t)(o0 + srw) * kw2 + kw];
                nwl = *(const uint4*)&Wl[(size_t)(o0 + srw) * kw2 + kw];
            }
            nah = *(const uint4*)&Ah[(nbase + srw) * kw2 + kw];
            nal = *(const uint4*)&Al[(nbase + srw) * kw2 + kw];
        }
        unsigned whf[2][4], wlf[2][4], bhf[2][2], blf[2][2];
        #pragma unroll
        for (int j = 0; j < 2; j++) {
            int r0 = j * 16 + g;
            whf[j][0] = s.wh[buf][r0][t];     whf[j][1] = s.wh[buf][r0 + 8][t];
            whf[j][2] = s.wh[buf][r0][t + 4]; whf[j][3] = s.wh[buf][r0 + 8][t + 4];
            wlf[j][0] = s.wl[buf][r0][t];     wlf[j][1] = s.wl[buf][r0 + 8][t];
            wlf[j][2] = s.wl[buf][r0][t + 4]; wlf[j][3] = s.wl[buf][r0 + 8][t + 4];
        }
        #pragma unroll
        for (int i = 0; i < 2; i++) {
            int n = wn0 + i * 8 + g;
            bhf[i][0] = s.ah[buf][n][t]; bhf[i][1] = s.ah[buf][n][t + 4];
            blf[i][0] = s.al[buf][n][t]; blf[i][1] = s.al[buf][n][t + 4];
        }
        #pragma unroll
        for (int j = 0; j < 2; j++)
            #pragma unroll
            for (int i = 0; i < 2; i++) {
                mma16816(d[j * 2 + i], whf[j], bhf[i]);
                mma16816(d[j * 2 + i], whf[j], blf[i]);
                mma16816(d[j * 2 + i], wlf[j], bhf[i]);
            }
        if (ks + 1 < KSTEPS) {
            if (tid < 64) {
                *(uint4*)&s.wh[buf ^ 1][srw][sq] = nwh;
                *(uint4*)&s.wl[buf ^ 1][srw][sq] = nwl;
            }
            *(uint4*)&s.ah[buf ^ 1][srw][sq] = nah;
            *(uint4*)&s.al[buf ^ 1][srw][sq] = nal;
        }
        barx(barid, 128);
        buf ^= 1;
    }
    #pragma unroll
    for (int j = 0; j < 2; j++)
        #pragma unroll
        for (int i = 0; i < 2; i++) {
            int nc = wn0 + i * 8 + 2 * t;
            s.outT[nc][j * 16 + g]     = d[j * 2 + i][0];
            s.outT[nc + 1][j * 16 + g] = d[j * 2 + i][1];
            s.outT[nc][j * 16 + g + 8]     = d[j * 2 + i][2];
            s.outT[nc + 1][j * 16 + g + 8] = d[j * 2 + i][3];
        }
    barx(barid, 128);
}

// ---------------- the persistent mega-kernel ----------------
__global__ __launch_bounds__(512, 1) void k_all(
    const float* __restrict__ pts, const float* __restrict__ rois,
    const float* __restrict__ feat,
    const float* __restrict__ Wm, const float* __restrict__ W1f,
    const float* __restrict__ W2f,
    const float* __restrict__ gm, const float* __restrict__ btm,
    const float* __restrict__ b1, const float* __restrict__ g1,
    const float* __restrict__ bt1, const float* __restrict__ b2,
    const float* __restrict__ g2, const float* __restrict__ bt2,
    float* __restrict__ out)
{
    extern __shared__ __align__(16) char dsm[];
    __shared__ float s_sc[256], s_sh[256];
    __shared__ float s_tt[32][33];
    int tid = threadIdx.x;

    // ================= PHASE A: stats zero + weight splits + feature split-transpose =================
    {
        int grp = tid >> 8;          // 0..1
        int gtid = tid & 255;
        float* tile = (float*)(dsm + grp * 12288);   // [64][33] floats
        for (int it = blockIdx.x * 2 + grp; it < 739; it += GRIDN * 2) {
            if (it < 227) {
                if (it == 0) {
                    for (int i = gtid; i < 1024; i += 256) g_stats[i] = 0.f;
                }
                int id = it * 256 + gtid;
                if (id < 32768) {
                    int o = id >> 7, c2 = id & 127;
                    unsigned lo;
                    unsigned hi = pack_split(Wm[o * 259 + 3 + 2 * c2], Wm[o * 259 + 4 + 2 * c2], lo);
                    g_Wfh[id] = hi; g_Wfl[id] = lo;
                } else if (id < 33536) {
                    int t2 = id - 32768; int o = t2 & 255, k = t2 >> 8;
                    g_WxT[t2] = Wm[o * 259 + k];
                } else if (id < 49920) {
                    int t2 = id - 33536; int o = t2 >> 7, c2 = t2 & 127;
                    unsigned lo;
                    unsigned hi = pack_split(W1f[o * 256 + 2 * c2], W1f[o * 256 + 2 * c2 + 1], lo);
                    g_W1h[t2] = hi; g_W1l[t2] = lo;
                } else if (id < 58112) {
                    int t2 = id - 49920; int o = t2 >> 6, c2 = t2 & 63;
                    unsigned lo;
                    unsigned hi = pack_split(W2f[o * 128 + 2 * c2], W2f[o * 128 + 2 * c2 + 1], lo);
                    g_W2h[t2] = hi; g_W2l[t2] = lo;
                }
            } else {
                int q2 = it - 227;              // 0..511
                int b = q2 >> 8;
                int rest = q2 & 255;
                int c0 = (rest >> 6) * 64;
                int n0 = (rest & 63) * 32;
                int tx = gtid & 31, ty = gtid >> 5;
                #pragma unroll
                for (int r8 = 0; r8 < 8; r8++) {
                    int row = r8 * 8 + ty;
                    tile[row * 33 + tx] = feat[(size_t)(b * 256 + c0 + row) * NN + n0 + tx];
                }
                barx(5 + grp, 256);
                int n_l = gtid >> 3;
                int c2_l = gtid & 7;
                #pragma unroll
                for (int q = 0; q < 4; q++) {
                    int c2 = q * 8 + c2_l;
                    unsigned lo;
                    unsigned hi = pack_split(tile[(2 * c2) * 33 + n_l], tile[(2 * c2 + 1) * 33 + n_l], lo);
                    size_t off = (size_t)(b * NN + n0 + n_l) * 128 + c0 / 2 + c2;
                    g_Fh[off] = hi; g_Fl[off] = lo;
                }
            }
            barx(5 + grp, 256);
        }
    }
    gridbar();

    // ================= PHASE B: gemmG (quarters) then neighbor scan + roi classify =================
    {
        int q = tid >> 7, qtid = tid & 127;
        SmemGemm* sg4 = (SmemGemm*)dsm;
        for (int t = blockIdx.x * 4 + q; t < 512; t += GRIDN * 4) {
            int b = t >> 8, r = t & 255;
            int n0 = (r & 31) * 64, o0 = (r >> 5) * 32;
            float d[4][4] = {};
            gemm_mainloopP<16>(sg4[q], g_Wfh, g_Wfl, g_Fh, g_Fl, o0,
                               (size_t)(b * NN + n0), d, qtid, 1 + q);
            int n_l = qtid >> 1, qq = qtid & 1;
            float* orow = &g_Gt[(size_t)(b * NN + n0 + n_l) * 256 + o0 + qq * 16];
            #pragma unroll
            for (int f = 0; f < 4; f++)
                *(float4*)&orow[f * 4] = *(float4*)&sg4[q].outT[n_l][qq * 16 + f * 4];
            barx(1 + q, 128);
        }
    }
    __syncthreads();
    {
        float* sx = (float*)dsm;
        float* sy = sx + NN;
        float* sz = sx + 2 * NN;
        int* cnt = (int*)(dsm + 3 * NN * 4);
        for (int it = blockIdx.x; it < 512; it += GRIDN) {
            if (it < 256) {
                // neighbor scan: 16 warps, warp per point
                int b = it >> 7, chunk = it & 127;
                const float* P = pts + (size_t)b * NN * 3;
                for (int j = tid; j < NN; j += 512) {
                    sx[j] = P[j * 3 + 0]; sy[j] = P[j * 3 + 1]; sz[j] = P[j * 3 + 2];
                }
                __syncthreads();
                int warp = tid >> 5, lane = tid & 31;
                int i = chunk * 16 + warp;
                float xi = sx[i], yi = sy[i], zi = sz[i];
                int base = (b * NN + i) * NSv;
                const float r2 = RADv * RADv;
                int c = 0, f0 = -1;
                for (int j0 = 0; j0 < NN; j0 += 32) {
                    int j = j0 + lane;
                    float dx = sx[j] - xi, dy = sy[j] - yi, dz = sz[j] - zi;
                    bool qq = (dx * dx + dy * dy + dz * dz) < r2;
                    unsigned m = __ballot_sync(0xffffffffu, qq);
                    if (m) {
                        if (f0 < 0) f0 = j0 + __ffs(m) - 1;
                        int pos = c + __popc(m & ((1u << lane) - 1u));
                        if (qq && pos < NSv) g_idx[base + pos] = j;
                        c += __popc(m);
                        if (c >= NSv) break;
                    }
                }
                if (c < NSv) {
                    for (int s = c + lane; s < NSv; s += 32) g_idx[base + s] = f0;
                }
            } else {
                // roi classify
                int br = it - 256;
                int b = br >> 7;
                if (tid == 0) *cnt = 0;
                __syncthreads();
                const float* qr = rois + (size_t)br * 7;
                float cx = qr[0], cy = qr[1], cz = qr[2];
                float hx = qr[3] * 0.5f, hy = qr[4] * 0.5f, hz = qr[5] * 0.5f;
                float co = cosf(qr[6]), si = sinf(qr[6]);
                const float* P = pts + (size_t)b * NN * 3;
                int* lst = g_roilst + (size_t)br * NN;
                for (int n = tid; n < NN; n += 512) {
                    float rx = P[n * 3 + 0] - cx;
                    float ry = P[n * 3 + 1] - cy;
                    float rz = P[n * 3 + 2] - cz;
                    float lx = rx * co + ry * si;
                    float ly = -rx * si + ry * co;
                    float lz = rz;
                    if (fabsf(lx) < hx && fabsf(ly) < hy && fabsf(lz) < hz) {
                        int v0 = (int)fminf(fmaxf(floorf((lx + hx) / (2.f * hx) * 5.f), 0.f), 4.f);
                        int v1 = (int)fminf(fmaxf(floorf((ly + hy) / (2.f * hy) * 5.f), 0.f), 4.f);
                        int v2 = (int)fminf(fmaxf(floorf((lz + hz) / (2.f * hz) * 5.f), 0.f), 4.f);
                        int vox = (v0 * 5 + v1) * 5 + v2;
                        int pos = atomicAdd(cnt, 1);
                        lst[pos] = (vox << 12) | n;
                    }
                }
                __syncthreads();
                if (tid == 0) g_roicnt[br] = *cnt;
            }
            __syncthreads();
        }
    }
    gridbar();

    // ================= PHASE C: gathermax (8 points/item, 1 point per 64-thread group) =================
    {
        int* sj    = (int*)dsm;
        float* srx = (float*)(dsm + 512);
        float* sry = (float*)(dsm + 1024);
        float* srz = (float*)(dsm + 1536);
        float* ssum = (float*)(dsm + 2048);          // [8][256]
        float* ssq  = (float*)(dsm + 2048 + 8192);   // [8][256]
        for (int it = blockIdx.x; it < 512; it += GRIDN) {
            int b = it >> 8, n0 = (it & 255) * 8;
            if (tid < 128) {
                int p = tid >> 4, sI = tid & 15;
                int n = n0 + p;
                int j = g_idx[(b * NN + n) * NSv + sI];
                sj[tid] = j;
                const float* P = pts + (size_t)b * NN * 3;
                srx[tid] = (P[j * 3 + 0] - P[n * 3 + 0]) / RADv;
                sry[tid] = (P[j * 3 + 1] - P[n * 3 + 1]) / RADv;
                srz[tid] = (P[j * 3 + 2] - P[n * 3 + 2]) / RADv;
            }
            __syncthreads();
            int co = tid & 63;
            int pg = tid >> 6;           // 0..7 -> point pg
            float4 w0 = *(const float4*)&g_WxT[co * 4];
            float4 w1 = *(const float4*)&g_WxT[256 + co * 4];
            float4 w2 = *(const float4*)&g_WxT[512 + co * 4];
            float4 ls = make_float4(0.f, 0.f, 0.f, 0.f);
            float4 lq = make_float4(0.f, 0.f, 0.f, 0.f);
            const float* Gb = g_Gt + (size_t)b * NN * 256;
            float4 m = make_float4(-3.4e38f, -3.4e38f, -3.4e38f, -3.4e38f);
            #pragma unroll
            for (int sI = 0; sI < NSv; sI++) {
                int e = pg * NSv + sI;
                int j = sj[e];
                float rx = srx[e], ry = sry[e], rz = srz[e];
                float4 gv = *(const float4*)&Gb[(size_t)j * 256 + co * 4];
                float4 v;
                v.x = gv.x + w0.x * rx + w1.x * ry + w2.x * rz;
                v.y = gv.y + w0.y * rx + w1.y * ry + w2.y * rz;
                v.z = gv.z + w0.z * rx + w1.z * ry + w2.z * rz;
                v.w = gv.w + w0.w * rx + w1.w * ry + w2.w * rz;
                m.x = fmaxf(m.x, v.x); m.y = fmaxf(m.y, v.y);
                m.z = fmaxf(m.z, v.z); m.w = fmaxf(m.w, v.w);
                ls.x += v.x; ls.y += v.y; ls.z += v.z; ls.w += v.w;
                lq.x += v.x * v.x; lq.y += v.y * v.y; lq.z += v.z * v.z; lq.w += v.w * v.w;
            }
            *(float4*)&g_hmax[(size_t)(b * NN + n0 + pg) * 256 + co * 4] = m;
            ssum[pg * 256 + co * 4 + 0] = ls.x; ssum[pg * 256 + co * 4 + 1] = ls.y;
            ssum[pg * 256 + co * 4 + 2] = ls.z; ssum[pg * 256 + co * 4 + 3] = ls.w;
            ssq[pg * 256 + co * 4 + 0] = lq.x; ssq[pg * 256 + co * 4 + 1] = lq.y;
            ssq[pg * 256 + co * 4 + 2] = lq.z; ssq[pg * 256 + co * 4 + 3] = lq.w;
            __syncthreads();
            if (tid < 256) {
                float ts = 0.f, tq = 0.f;
                #pragma unroll
                for (int g = 0; g < 8; g++) { ts += ssum[g * 256 + tid]; tq += ssq[g * 256 + tid]; }
                atomicAdd(&g_stats[tid], ts);
                atomicAdd(&g_stats[256 + tid], tq);
            }
            __syncthreads();
        }
    }
    gridbar();

    // ================= PHASE D: conv1 (BN1+ReLU+split) =================
    if (tid < 256) {
        float m = g_stats[tid] * (1.f / 65536.f);
        float v = g_stats[256 + tid] * (1.f / 65536.f) - m * m;
        float sc = gm[tid] * rsqrtf(v + EPSv);
        s_sc[tid] = sc; s_sh[tid] = btm[tid] - m * sc;
    }
    __syncthreads();
    for (int it = blockIdx.x; it < 128; it += GRIDN) {
        int base = it * 32 + (tid >> 6);     // rows base, +8, +16, +24
        int c4 = (tid & 63) * 4;
        float sc0 = s_sc[c4], sc1 = s_sc[c4 + 1], sc2 = s_sc[c4 + 2], sc3 = s_sc[c4 + 3];
        float sh0 = s_sh[c4], sh1 = s_sh[c4 + 1], sh2 = s_sh[c4 + 2], sh3 = s_sh[c4 + 3];
        float4 v[4];
        #pragma unroll
        for (int i = 0; i < 4; i++)
            v[i] = *(const float4*)&g_hmax[(size_t)(base + i * 8) * 256 + c4];
        #pragma unroll
        for (int i = 0; i < 4; i++) {
            float x0 = fmaxf(v[i].x * sc0 + sh0, 0.f);
            float x1 = fmaxf(v[i].y * sc1 + sh1, 0.f);
            float x2 = fmaxf(v[i].z * sc2 + sh2, 0.f);
            float x3 = fmaxf(v[i].w * sc3 + sh3, 0.f);
            unsigned lo0, lo1;
            unsigned hi0 = pack_split(x0, x1, lo0);
            unsigned hi1 = pack_split(x2, x3, lo1);
            size_t bn = (size_t)(base + i * 8);
            *(uint2*)&g_A1h[bn * 128 + c4 / 2] = make_uint2(hi0, hi1);
            *(uint2*)&g_A1l[bn * 128 + c4 / 2] = make_uint2(lo0, lo1);
        }
    }
    gridbar();

    // ================= PHASE E: GEMM1 (quarters) + BN2 stats =================
    {
        int q = tid >> 7, qtid = tid & 127;
        SmemGemm* sg4 = (SmemGemm*)dsm;
        for (int t = blockIdx.x * 4 + q; t < 256; t += GRIDN * 4) {
            int b = t >> 7, r = t & 127;
            int n0 = (r & 31) * 64, o0 = (r >> 5) * 32;
            float d[4][4] = {};
            gemm_mainloopP<16>(sg4[q], g_W1h, g_W1l, g_A1h, g_A1l, o0,
                               (size_t)(b * NN + n0), d, qtid, 1 + q);
            int o_l = qtid & 31, chunk = qtid >> 5;
            int o = o0 + o_l;
            float bias = b1[o];
            float sum = 0.f, sq = 0.f;
            #pragma unroll
            for (int r2 = 0; r2 < 16; r2++) {
                int n = chunk * 16 + r2;
                float v = sg4[q].outT[n][o_l] + bias;
                sum += v; sq += v * v;
                g_h2[(size_t)(b * NN + n0 + n) * C1v + o] = v;
            }
            atomicAdd(&g_stats[512 + o], sum);
            atomicAdd(&g_stats[640 + o], sq);
            barx(1 + q, 128);
        }
    }
    gridbar();

    // ================= PHASE F: conv2 (BN2+ReLU+split) =================
    if (tid < 128) {
        float m = g_stats[512 + tid] * (1.f / 4096.f);
        float v = g_stats[640 + tid] * (1.f / 4096.f) - m * m;
        float sc = g1[tid] * rsqrtf(v + EPSv);
        s_sc[tid] = sc; s_sh[tid] = bt1[tid] - m * sc;
    }
    __syncthreads();
    for (int it = blockIdx.x; it < 64; it += GRIDN) {
        int base = it * 64 + (tid >> 5);     // rows base, +16, +32, +48
        int c4 = (tid & 31) * 4;
        float sc0 = s_sc[c4], sc1 = s_sc[c4 + 1], sc2 = s_sc[c4 + 2], sc3 = s_sc[c4 + 3];
        float sh0 = s_sh[c4], sh1 = s_sh[c4 + 1], sh2 = s_sh[c4 + 2], sh3 = s_sh[c4 + 3];
        float4 v[4];
        #pragma unroll
        for (int i = 0; i < 4; i++)
            v[i] = *(const float4*)&g_h2[(size_t)(base + i * 16) * 128 + c4];
        #pragma unroll
        for (int i = 0; i < 4; i++) {
            float x0 = fmaxf(v[i].x * sc0 + sh0, 0.f);
            float x1 = fmaxf(v[i].y * sc1 + sh1, 0.f);
            float x2 = fmaxf(v[i].z * sc2 + sh2, 0.f);
            float x3 = fmaxf(v[i].w * sc3 + sh3, 0.f);
            unsigned lo0, lo1;
            unsigned hi0 = pack_split(x0, x1, lo0);
            unsigned hi1 = pack_split(x2, x3, lo1);
            size_t bn = (size_t)(base + i * 16);
            *(uint2*)&g_A2h[bn * 64 + c4 / 2] = make_uint2(hi0, hi1);
            *(uint2*)&g_A2l[bn * 64 + c4 / 2] = make_uint2(lo0, lo1);
        }
    }
    gridbar();

    // ================= PHASE G: GEMM2 (quarters) + BN3 stats =================
    {
        int q = tid >> 7, qtid = tid & 127;
        SmemGemm* sg4 = (SmemGemm*)dsm;
        for (int t = blockIdx.x * 4 + q; t < 256; t += GRIDN * 4) {
            int b = t >> 7, r = t & 127;
            int n0 = (r & 31) * 64, o0 = (r >> 5) * 32;
            float d[4][4] = {};
            gemm_mainloopP<8>(sg4[q], g_W2h, g_W2l, g_A2h, g_A2l, o0,
                              (size_t)(b * NN + n0), d, qtid, 1 + q);
            int o_l = qtid & 31, chunk = qtid >> 5;
            int o = o0 + o_l;
            float bias = b2[o];
            float sum = 0.f, sq = 0.f;
            #pragma unroll
            for (int r2 = 0; r2 < 16; r2++) {
                int n = chunk * 16 + r2;
                float v = sg4[q].outT[n][o_l] + bias;
                sum += v; sq += v * v;
                g_h3[(size_t)(b * NN + n0 + n) * C1v + o] = v;
            }
            atomicAdd(&g_stats[768 + o], sum);
            atomicAdd(&g_stats[896 + o], sq);
            barx(1 + q, 128);
        }
    }
    gridbar();

    // ================= PHASE H: roipool (inline BN3) + feats output =================
    if (tid < 128) {
        float m = g_stats[768 + tid] * (1.f / 4096.f);
        float v = g_stats[896 + tid] * (1.f / 4096.f) - m * m;
        float sc = g2[tid] * rsqrtf(v + EPSv);
        s_sc[tid] = sc; s_sh[tid] = bt2[tid] - m * sc;
    }
    __syncthreads();
    {
        float* sg = (float*)dsm;            // 125*128 floats
        for (int it = blockIdx.x; it < 768; it += GRIDN) {
            if (it < 256) {
                int br = it;
                int b = br >> 7;
                for (int i = tid; i < 125 * C1v / 4; i += 512)
                    ((float4*)sg)[i] = make_float4(0.f, 0.f, 0.f, 0.f);
                __syncthreads();
                const float* H = g_h3 + (size_t)b * NN * C1v;
                const int* lst = g_roilst + (size_t)br * NN;
                int m = g_roicnt[br];
                int ch = tid & 127;
                int slot = tid >> 7;
                float sc = s_sc[ch], sh = s_sh[ch];
                for (int e = slot; e < m; e += 4) {
                    int pk = lst[e];
                    int n = pk & 4095;
                    int vox = pk >> 12;
                    float val = fmaxf(H[(size_t)n * C1v + ch] * sc + sh, 0.f);
                    atomicMax((int*)&sg[vox * C1v + ch], __float_as_int(val));
                }
                __syncthreads();
                float4* og = (float4*)(out + FEATS_SZ + (size_t)br * 125 * C1v);
                for (int i = tid; i < 125 * C1v / 4; i += 512) og[i] = ((float4*)sg)[i];
            } else {
                int q = it - 256;            // 0..511
                int b = q >> 8;
                int rest = q & 255;
                int n0 = (rest & 63) * 32, o0 = (rest >> 6) * 32;
                int tx = tid & 31, ty = tid >> 5;    // 32 x 16
                #pragma unroll
                for (int r = 0; r < 2; r++) {
                    int n_l = ty + r * 16;
                    int o = o0 + tx;
                    float f = fmaxf(g_h3[(size_t)(b * NN + n0 + n_l) * C1v + o] * s_sc[o] + s_sh[o], 0.f);
                    s_tt[n_l][tx] = f;
                }
                __syncthreads();
                #pragma unroll
                for (int r = 0; r < 2; r++) {
                    int o_l = ty + r * 16;
                    out[(size_t)(b * C1v + o0 + o_l) * NN + n0 + tx] = s_tt[tx][o_l];
                }
            }
            __syncthreads();
        }
    }
}

// ---------------- launch ----------------
extern "C" void kernel_launch(void* const* d_in, const int* in_sizes, int n_in,
                              void* d_out, int out_size) {
    const float* pts    = (const float*)d_in[0];
    const float* feat   = (const float*)d_in[1];
    const float* rois   = (const float*)d_in[2];
    const float* W_mlp  = (const float*)d_in[3];
    const float* g_mlp  = (const float*)d_in[4];
    const float* btm    = (const float*)d_in[5];
    const float* W1     = (const float*)d_in[6];
    const float* b1     = (const float*)d_in[7];
    const float* g1     = (const float*)d_in[8];
    const float* bt1    = (const float*)d_in[9];
    const float* W2     = (const float*)d_in[10];
    const float* b2     = (const float*)d_in[11];
    const float* g2     = (const float*)d_in[12];
    const float* bt2    = (const float*)d_in[13];
    float* out = (float*)d_out;

    int dyn = (int)(4 * sizeof(SmemGemm));   // 110592 bytes (covers all phases)
    cudaFuncSetAttribute(k_all, cudaFuncAttributeMaxDynamicSharedMemorySize, dyn);

    k_all<<<GRIDN, 512, dyn>>>(pts, rois, feat, W_mlp, W1, W2,
                               g_mlp, btm, b1, g1, bt1, b2, g2, bt2, out);
}

// round 14
// speedup vs baseline: 1.3355x; 1.3355x over previous
#include <cuda_runtime.h>
#include <cuda_bf16.h>
#include <math.h>

// Problem constants
#define BB   2
#define NN   2048
#define RRoi 128
#define CINv 256
#define NSv  16
#define C1v  128
#define RADv 0.3f
#define EPSv 1e-5f
#define FEATS_SZ (BB*C1v*NN)          // 524288

// ---------------- scratch ----------------
__device__ int   g_idx[BB*NN*NSv];
__device__ float g_Gt[BB*NN*256];        // [b][n][o]
__device__ float g_hmax[BB*NN*256];      // [b][n][c]
__device__ float g_h2[BB*NN*C1v];        // [b][n][o]
__device__ float g_h3[BB*NN*C1v];        // [b][n][o]
__device__ float g_WxT[3*256];           // [k][o]
__device__ unsigned g_Wfh[256*128], g_Wfl[256*128];
__device__ unsigned g_W1h[128*128], g_W1l[128*128];
__device__ unsigned g_W2h[128*64],  g_W2l[128*64];
__device__ unsigned g_Fh[BB*NN*128],  g_Fl[BB*NN*128];
__device__ unsigned g_A1h[BB*NN*128], g_A1l[BB*NN*128];
__device__ unsigned g_A2h[BB*NN*64],  g_A2l[BB*NN*64];
__device__ int   g_roilst[BB*RRoi*NN];
__device__ int   g_roicnt[BB*RRoi];
__device__ float g_stats[1024];

// ---------------- helpers ----------------
__device__ __forceinline__ unsigned pack_split(float x0, float x1, unsigned& lo) {
    __nv_bfloat16 h0 = __float2bfloat16(x0);
    __nv_bfloat16 h1 = __float2bfloat16(x1);
    __nv_bfloat16 l0 = __float2bfloat16(x0 - __bfloat162float(h0));
    __nv_bfloat16 l1 = __float2bfloat16(x1 - __bfloat162float(h1));
    lo = ((unsigned)__bfloat16_as_ushort(l1) << 16) | (unsigned)__bfloat16_as_ushort(l0);
    return ((unsigned)__bfloat16_as_ushort(h1) << 16) | (unsigned)__bfloat16_as_ushort(h0);
}

__device__ __forceinline__ void mma16816(float* d, const unsigned* a, const unsigned* b) {
    asm volatile(
        "mma.sync.aligned.m16n8k16.row.col.f32.bf16.bf16.f32 "
        "{%0,%1,%2,%3}, {%4,%5,%6,%7}, {%8,%9}, {%0,%1,%2,%3};"
        : "+f"(d[0]), "+f"(d[1]), "+f"(d[2]), "+f"(d[3])
        : "r"(a[0]), "r"(a[1]), "r"(a[2]), "r"(a[3]), "r"(b[0]), "r"(b[1]));
}

struct SmemGemm {
    unsigned wh[2][32][12], wl[2][32][12];
    unsigned ah[2][64][12], al[2][64][12];
    float outT[64][36];
};

// pure-MMA mainloop: 32o x 64n tile, 128 threads (R10-proven)
template<int KSTEPS>
__device__ __forceinline__ void gemm_mainloop(
    SmemGemm& s,
    const unsigned* __restrict__ Wh, const unsigned* __restrict__ Wl,
    const unsigned* __restrict__ Ah, const unsigned* __restrict__ Al,
    int o0, size_t nbase, float (*d)[4], int tid)
{
    const int kw2 = KSTEPS * 8;
    int lane = tid & 31, warp = tid >> 5;
    int g = lane >> 2, t = lane & 3;
    int wn0 = warp * 16;
    int srw = tid >> 1;
    int sq = (tid & 1) * 4;
    if (tid < 64) {
        *(uint4*)&s.wh[0][srw][sq] = *(const uint4*)&Wh[(size_t)(o0 + srw) * kw2 + sq];
        *(uint4*)&s.wl[0][srw][sq] = *(const uint4*)&Wl[(size_t)(o0 + srw) * kw2 + sq];
    }
    *(uint4*)&s.ah[0][srw][sq] = *(const uint4*)&Ah[(nbase + srw) * kw2 + sq];
    *(uint4*)&s.al[0][srw][sq] = *(const uint4*)&Al[(nbase + srw) * kw2 + sq];
    __syncthreads();
    int buf = 0;
    #pragma unroll
    for (int ks = 0; ks < KSTEPS; ks++) {
        uint4 nwh, nwl, nah, nal;
        if (ks + 1 < KSTEPS) {
            int kw = (ks + 1) * 8 + sq;
            if (tid < 64) {
                nwh = *(const uint4*)&Wh[(size_t)(o0 + srw) * kw2 + kw];
                nwl = *(const uint4*)&Wl[(size_t)(o0 + srw) * kw2 + kw];
            }
            nah = *(const uint4*)&Ah[(nbase + srw) * kw2 + kw];
            nal = *(const uint4*)&Al[(nbase + srw) * kw2 + kw];
        }
        unsigned whf[2][4], wlf[2][4], bhf[2][2], blf[2][2];
        #pragma unroll
        for (int j = 0; j < 2; j++) {
            int r0 = j * 16 + g;
            whf[j][0] = s.wh[buf][r0][t];     whf[j][1] = s.wh[buf][r0 + 8][t];
            whf[j][2] = s.wh[buf][r0][t + 4]; whf[j][3] = s.wh[buf][r0 + 8][t + 4];
            wlf[j][0] = s.wl[buf][r0][t];     wlf[j][1] = s.wl[buf][r0 + 8][t];
            wlf[j][2] = s.wl[buf][r0][t + 4]; wlf[j][3] = s.wl[buf][r0 + 8][t + 4];
        }
        #pragma unroll
        for (int i = 0; i < 2; i++) {
            int n = wn0 + i * 8 + g;
            bhf[i][0] = s.ah[buf][n][t]; bhf[i][1] = s.ah[buf][n][t + 4];
            blf[i][0] = s.al[buf][n][t]; blf[i][1] = s.al[buf][n][t + 4];
        }
        #pragma unroll
        for (int j = 0; j < 2; j++)
            #pragma unroll
            for (int i = 0; i < 2; i++) {
                mma16816(d[j * 2 + i], whf[j], bhf[i]);
                mma16816(d[j * 2 + i], whf[j], blf[i]);
                mma16816(d[j * 2 + i], wlf[j], bhf[i]);
            }
        if (ks + 1 < KSTEPS) {
            if (tid < 64) {
                *(uint4*)&s.wh[buf ^ 1][srw][sq] = nwh;
                *(uint4*)&s.wl[buf ^ 1][srw][sq] = nwl;
            }
            *(uint4*)&s.ah[buf ^ 1][srw][sq] = nah;
            *(uint4*)&s.al[buf ^ 1][srw][sq] = nal;
        }
        __syncthreads();
        buf ^= 1;
    }
    #pragma unroll
    for (int j = 0; j < 2; j++)
        #pragma unroll
        for (int i = 0; i < 2; i++) {
            int nc = wn0 + i * 8 + 2 * t;
            s.outT[nc][j * 16 + g]     = d[j * 2 + i][0];
            s.outT[nc + 1][j * 16 + g] = d[j * 2 + i][1];
            s.outT[nc][j * 16 + g + 8]     = d[j * 2 + i][2];
            s.outT[nc + 1][j * 16 + g + 8] = d[j * 2 + i][3];
        }
    __syncthreads();
}

// ---------------- frontA: stats zero + weight splits + feature split-transpose ----------------
__global__ void k_frontA(const float* __restrict__ feat,
                         const float* __restrict__ Wm, const float* __restrict__ W1,
                         const float* __restrict__ W2) {
    __shared__ __align__(16) float tile[64 * 33];
    int blk = blockIdx.x;
    if (blk < 227) {
        if (blk == 0) {
            for (int i = threadIdx.x; i < 1024; i += 256) g_stats[i] = 0.f;
        }
        int id = blk * 256 + threadIdx.x;          // < 58112
        if (id < 32768) {
            int o = id >> 7, c2 = id & 127;
            unsigned lo;
            unsigned hi = pack_split(Wm[o * 259 + 3 + 2 * c2], Wm[o * 259 + 4 + 2 * c2], lo);
            g_Wfh[id] = hi; g_Wfl[id] = lo;
        } else if (id < 33536) {
            int t2 = id - 32768; int o = t2 & 255, k = t2 >> 8;
            g_WxT[t2] = Wm[o * 259 + k];
        } else if (id < 49920) {
            int t2 = id - 33536; int o = t2 >> 7, c2 = t2 & 127;
            unsigned lo;
            unsigned hi = pack_split(W1[o * 256 + 2 * c2], W1[o * 256 + 2 * c2 + 1], lo);
            g_W1h[t2] = hi; g_W1l[t2] = lo;
        } else if (id < 58112) {
            int t2 = id - 49920; int o = t2 >> 6, c2 = t2 & 63;
            unsigned lo;
            unsigned hi = pack_split(W2[o * 128 + 2 * c2], W2[o * 128 + 2 * c2 + 1], lo);
            g_W2h[t2] = hi; g_W2l[t2] = lo;
        }
    } else {
        // feature split-transpose: feat[b][c][n] fp32 -> g_Fh/Fl [b][n][c/2]
        int q2 = blk - 227;                 // 0..511
        int b = q2 >> 8;
        int rest = q2 & 255;
        int c0 = (rest >> 6) * 64;
        int n0 = (rest & 63) * 32;
        int tx = threadIdx.x & 31, ty = threadIdx.x >> 5;
        #pragma unroll
        for (int r8 = 0; r8 < 8; r8++) {
            int row = r8 * 8 + ty;
            tile[row * 33 + tx] = feat[(size_t)(b * 256 + c0 + row) * NN + n0 + tx];
        }
        __syncthreads();
        int n_l = threadIdx.x >> 3;
        int c2_l = threadIdx.x & 7;
        #pragma unroll
        for (int q = 0; q < 4; q++) {
            int c2 = q * 8 + c2_l;
            unsigned lo;
            unsigned hi = pack_split(tile[(2 * c2) * 33 + n_l], tile[(2 * c2 + 1) * 33 + n_l], lo);
            size_t off = (size_t)(b * NN + n0 + n_l) * 128 + c0 / 2 + c2;
            g_Fh[off] = hi; g_Fl[off] = lo;
        }
    }
}

// ---------------- frontB: neighbor scan + roi classify (side stream) ----------------
__global__ void k_frontB(const float* __restrict__ pts, const float* __restrict__ rois) {
    __shared__ __align__(16) char sbuf[24576];
    int blk = blockIdx.x;
    if (blk < 512) {
        // neighbor search: warp-per-point ballot scan
        int b = blk >> 8, chunk = blk & 255;
        float* sx = (float*)sbuf;
        float* sy = sx + NN;
        float* sz = sx + 2 * NN;
        const float* P = pts + (size_t)b * NN * 3;
        for (int j = threadIdx.x; j < NN; j += 256) {
            sx[j] = P[j * 3 + 0]; sy[j] = P[j * 3 + 1]; sz[j] = P[j * 3 + 2];
        }
        __syncthreads();
        int warp = threadIdx.x >> 5, lane = threadIdx.x & 31;
        int i = chunk * 8 + warp;
        float xi = sx[i], yi = sy[i], zi = sz[i];
        int base = (b * NN + i) * NSv;
        const float r2 = RADv * RADv;
        int cnt = 0, f0 = -1;
        for (int j0 = 0; j0 < NN; j0 += 32) {
            int j = j0 + lane;
            float dx = sx[j] - xi, dy = sy[j] - yi, dz = sz[j] - zi;
            bool qq = (dx * dx + dy * dy + dz * dz) < r2;
            unsigned m = __ballot_sync(0xffffffffu, qq);
            if (m) {
                if (f0 < 0) f0 = j0 + __ffs(m) - 1;
                int pos = cnt + __popc(m & ((1u << lane) - 1u));
                if (qq && pos < NSv) g_idx[base + pos] = j;
                cnt += __popc(m);
                if (cnt >= NSv) break;
            }
        }
        if (cnt < NSv) {
            for (int s = cnt + lane; s < NSv; s += 32) g_idx[base + s] = f0;
        }
    } else {
        // roi point-in-box classify
        int br = blk - 512;
        int b = br >> 7;
        int* cnt = (int*)sbuf;
        if (threadIdx.x == 0) *cnt = 0;
        __syncthreads();
        const float* qr = rois + (size_t)br * 7;
        float cx = qr[0], cy = qr[1], cz = qr[2];
        float hx = qr[3] * 0.5f, hy = qr[4] * 0.5f, hz = qr[5] * 0.5f;
        float co = cosf(qr[6]), si = sinf(qr[6]);
        const float* P = pts + (size_t)b * NN * 3;
        int* lst = g_roilst + (size_t)br * NN;
        for (int n = threadIdx.x; n < NN; n += 256) {
            float rx = P[n * 3 + 0] - cx;
            float ry = P[n * 3 + 1] - cy;
            float rz = P[n * 3 + 2] - cz;
            float lx = rx * co + ry * si;
            float ly = -rx * si + ry * co;
            float lz = rz;
            if (fabsf(lx) < hx && fabsf(ly) < hy && fabsf(lz) < hz) {
                int v0 = (int)fminf(fmaxf(floorf((lx + hx) / (2.f * hx) * 5.f), 0.f), 4.f);
                int v1 = (int)fminf(fmaxf(floorf((ly + hy) / (2.f * hy) * 5.f), 0.f), 4.f);
                int v2 = (int)fminf(fmaxf(floorf((lz + hz) / (2.f * hz) * 5.f), 0.f), 4.f);
                int vox = (v0 * 5 + v1) * 5 + v2;
                int pos = atomicAdd(cnt, 1);
                lst[pos] = (vox << 12) | n;
            }
        }
        __syncthreads();
        if (threadIdx.x == 0) g_roicnt[br] = *cnt;
    }
}

// ---------------- GEMM G: Gt[b][n][o] = Wf @ feat, pure MMA ----------------
__global__ void k_gemmG() {
    __shared__ SmemGemm s;
    int b = blockIdx.z;
    int n0 = blockIdx.x * 64, o0 = blockIdx.y * 32;
    int tid = threadIdx.x;
    float d[4][4] = {};
    gemm_mainloop<16>(s, g_Wfh, g_Wfl, g_Fh, g_Fl, o0, (size_t)(b * NN + n0), d, tid);
    int n_l = tid >> 1, q = tid & 1;
    float* orow = &g_Gt[(size_t)(b * NN + n0 + n_l) * 256 + o0 + q * 16];
    #pragma unroll
    for (int f = 0; f < 4; f++)
        *(float4*)&orow[f * 4] = *(float4*)&s.outT[n_l][q * 16 + f * 4];
}

// ---------------- gather + xyz MLP + max + BN1 stats (writes hmax [b][n][c]) ----------------
#define PPB 8
__global__ void k_gathermax(const float* __restrict__ pts) {
    __shared__ int   sj[PPB * NSv];
    __shared__ float srx[PPB * NSv], sry[PPB * NSv], srz[PPB * NSv];
    __shared__ float ssum[4][256], ssq[4][256];
    int b = blockIdx.y;
    int n0 = blockIdx.x * PPB;
    int tid = threadIdx.x;
    if (tid < PPB * NSv) {
        int p = tid >> 4, sI = tid & 15;
        int n = n0 + p;
        int j = g_idx[(b * NN + n) * NSv + sI];
        sj[tid] = j;
        const float* P = pts + (size_t)b * NN * 3;
        srx[tid] = (P[j * 3 + 0] - P[n * 3 + 0]) / RADv;
        sry[tid] = (P[j * 3 + 1] - P[n * 3 + 1]) / RADv;
        srz[tid] = (P[j * 3 + 2] - P[n * 3 + 2]) / RADv;
    }
    __syncthreads();
    int co = tid & 63;
    int pg = tid >> 6;
    float4 w0 = *(const float4*)&g_WxT[co * 4];
    float4 w1 = *(const float4*)&g_WxT[256 + co * 4];
    float4 w2 = *(const float4*)&g_WxT[512 + co * 4];
    float4 ls = make_float4(0.f, 0.f, 0.f, 0.f);
    float4 lq = make_float4(0.f, 0.f, 0.f, 0.f);
    const float* Gb = g_Gt + (size_t)b * NN * 256;
    #pragma unroll
    for (int pp = 0; pp < 2; pp++) {
        int p = pg * 2 + pp;
        float4 m = make_float4(-3.4e38f, -3.4e38f, -3.4e38f, -3.4e38f);
        #pragma unroll
        for (int sI = 0; sI < NSv; sI++) {
            int e = p * NSv + sI;
            int j = sj[e];
            float rx = srx[e], ry = sry[e], rz = srz[e];
            float4 gv = *(const float4*)&Gb[(size_t)j * 256 + co * 4];
            float4 v;
            v.x = gv.x + w0.x * rx + w1.x * ry + w2.x * rz;
            v.y = gv.y + w0.y * rx + w1.y * ry + w2.y * rz;
            v.z = gv.z + w0.z * rx + w1.z * ry + w2.z * rz;
            v.w = gv.w + w0.w * rx + w1.w * ry + w2.w * rz;
            m.x = fmaxf(m.x, v.x); m.y = fmaxf(m.y, v.y);
            m.z = fmaxf(m.z, v.z); m.w = fmaxf(m.w, v.w);
            ls.x += v.x; ls.y += v.y; ls.z += v.z; ls.w += v.w;
            lq.x += v.x * v.x; lq.y += v.y * v.y; lq.z += v.z * v.z; lq.w += v.w * v.w;
        }
        *(float4*)&g_hmax[(size_t)(b * NN + n0 + p) * 256 + co * 4] = m;
    }
    ssum[pg][co * 4 + 0] = ls.x; ssum[pg][co * 4 + 1] = ls.y;
    ssum[pg][co * 4 + 2] = ls.z; ssum[pg][co * 4 + 3] = ls.w;
    ssq[pg][co * 4 + 0] = lq.x; ssq[pg][co * 4 + 1] = lq.y;
    ssq[pg][co * 4 + 2] = lq.z; ssq[pg][co * 4 + 3] = lq.w;
    __syncthreads();
    float ts = ssum[0][tid] + ssum[1][tid] + ssum[2][tid] + ssum[3][tid];
    float tq = ssq[0][tid] + ssq[1][tid] + ssq[2][tid] + ssq[3][tid];
    atomicAdd(&g_stats[tid], ts);
    atomicAdd(&g_stats[256 + tid], tq);
}

// ---------------- conv1: relu(bn1(hmax)) -> split bf16, 1 row/thread, grid 1024 (R9-best) ----------------
__global__ void k_conv1(const float* __restrict__ gm, const float* __restrict__ btm) {
    __shared__ float ssc[256], ssh[256];
    int tid = threadIdx.x;
    {
        float m = g_stats[tid] * (1.f / 65536.f);
        float v = g_stats[256 + tid] * (1.f / 65536.f) - m * m;
        float sc = gm[tid] * rsqrtf(v + EPSv);
        ssc[tid] = sc; ssh[tid] = btm[tid] - m * sc;
    }
    __syncthreads();
    int bn = blockIdx.x * 4 + (tid >> 6);
    int c4 = (tid & 63) * 4;
    float4 v = *(const float4*)&g_hmax[(size_t)bn * 256 + c4];
    float x0 = fmaxf(v.x * ssc[c4] + ssh[c4], 0.f);
    float x1 = fmaxf(v.y * ssc[c4 + 1] + ssh[c4 + 1], 0.f);
    float x2 = fmaxf(v.z * ssc[c4 + 2] + ssh[c4 + 2], 0.f);
    float x3 = fmaxf(v.w * ssc[c4 + 3] + ssh[c4 + 3], 0.f);
    unsigned lo0, lo1;
    unsigned hi0 = pack_split(x0, x1, lo0);
    unsigned hi1 = pack_split(x2, x3, lo1);
    *(uint2*)&g_A1h[(size_t)bn * 128 + c4 / 2] = make_uint2(hi0, hi1);
    *(uint2*)&g_A1l[(size_t)bn * 128 + c4 / 2] = make_uint2(lo0, lo1);
}

// ---------------- GEMM1: h2[b][n][o] = b1 + W1 @ A1, fused BN2 stats ----------------
__global__ void k_gemm1(const float* __restrict__ b1) {
    __shared__ SmemGemm s;
    int b = blockIdx.z;
    int n0 = blockIdx.x * 64, o0 = blockIdx.y * 32;
    int tid = threadIdx.x;
    float d[4][4] = {};
    gemm_mainloop<16>(s, g_W1h, g_W1l, g_A1h, g_A1l, o0, (size_t)(b * NN + n0), d, tid);
    int o_l = tid & 31, chunk = tid >> 5;
    int o = o0 + o_l;
    float bias = b1[o];
    float sum = 0.f, sq = 0.f;
    #pragma unroll
    for (int r = 0; r < 16; r++) {
        int n = chunk * 16 + r;
        float v = s.outT[n][o_l] + bias;
        sum += v; sq += v * v;
        g_h2[(size_t)(b * NN + n0 + n) * C1v + o] = v;
    }
    atomicAdd(&g_stats[512 + o], sum);
    atomicAdd(&g_stats[640 + o], sq);
}

// ---------------- conv2: relu(bn2(h2)) -> split bf16, 1 row/thread, grid 512 (R9-best) ----------------
__global__ void k_conv2(const float* __restrict__ g1, const float* __restrict__ bt1) {
    __shared__ float ssc[128], ssh[128];
    int tid = threadIdx.x;
    if (tid < 128) {
        float m = g_stats[512 + tid] * (1.f / 4096.f);
        float v = g_stats[640 + tid] * (1.f / 4096.f) - m * m;
        float sc = g1[tid] * rsqrtf(v + EPSv);
        ssc[tid] = sc; ssh[tid] = bt1[tid] - m * sc;
    }
    __syncthreads();
    int bn = blockIdx.x * 8 + (tid >> 5);
    int c4 = (tid & 31) * 4;
    float4 v = *(const float4*)&g_h2[(size_t)bn * 128 + c4];
    float x0 = fmaxf(v.x * ssc[c4] + ssh[c4], 0.f);
    float x1 = fmaxf(v.y * ssc[c4 + 1] + ssh[c4 + 1], 0.f);
    float x2 = fmaxf(v.z * ssc[c4 + 2] + ssh[c4 + 2], 0.f);
    float x3 = fmaxf(v.w * ssc[c4 + 3] + ssh[c4 + 3], 0.f);
    unsigned lo0, lo1;
    unsigned hi0 = pack_split(x0, x1, lo0);
    unsigned hi1 = pack_split(x2, x3, lo1);
    *(uint2*)&g_A2h[(size_t)bn * 64 + c4 / 2] = make_uint2(hi0, hi1);
    *(uint2*)&g_A2l[(size_t)bn * 64 + c4 / 2] = make_uint2(lo0, lo1);
}

// ---------------- GEMM2: h3[b][n][o] = b2 + W2 @ A2, fused BN3 stats ----------------
__global__ void k_gemm2(const float* __restrict__ b2) {
    __shared__ SmemGemm s;
    int b = blockIdx.z;
    int n0 = blockIdx.x * 64, o0 = blockIdx.y * 32;
    int tid = threadIdx.x;
    float d[4][4] = {};
    gemm_mainloop<8>(s, g_W2h, g_W2l, g_A2h, g_A2l, o0, (size_t)(b * NN + n0), d, tid);
    int o_l = tid & 31, chunk = tid >> 5;
    int o = o0 + o_l;
    float bias = b2[o];
    float sum = 0.f, sq = 0.f;
    #pragma unroll
    for (int r = 0; r < 16; r++) {
        int n = chunk * 16 + r;
        float v = s.outT[n][o_l] + bias;
        sum += v; sq += v * v;
        g_h3[(size_t)(b * NN + n0 + n) * C1v + o] = v;
    }
    atomicAdd(&g_stats[768 + o], sum);
    atomicAdd(&g_stats[896 + o], sq);
}

// ---------------- final: roipool (inline BN3 from h3) + feats output, merged ----------------
__global__ void k_final(const float* __restrict__ g2, const float* __restrict__ bt2,
                        float* __restrict__ out) {
    extern __shared__ float sg[];            // 125*128 floats (roipool blocks)
    __shared__ float ssc[128], ssh[128];
    __shared__ float tt[32][33];
    int blk = blockIdx.x;
    int tid = threadIdx.x;                   // 512
    if (tid < 128) {
        float m = g_stats[768 + tid] * (1.f / 4096.f);
        float v = g_stats[896 + tid] * (1.f / 4096.f) - m * m;
        float sc = g2[tid] * rsqrtf(v + EPSv);
        ssc[tid] = sc; ssh[tid] = bt2[tid] - m * sc;
    }
    __syncthreads();
    if (blk < BB * RRoi) {
        int br = blk;
        int b = br >> 7;
        for (int i = tid; i < 125 * C1v / 4; i += 512)
            ((float4*)sg)[i] = make_float4(0.f, 0.f, 0.f, 0.f);
        __syncthreads();
        const float* H = g_h3 + (size_t)b * NN * C1v;
        const int* lst = g_roilst + (size_t)br * NN;
        int m = g_roicnt[br];
        int ch = tid & 127;
        int slot = tid >> 7;
        float sc = ssc[ch], sh = ssh[ch];
        for (int e = slot; e < m; e += 4) {
            int pk = lst[e];
            int n = pk & 4095;
            int vox = pk >> 12;
            float val = fmaxf(H[(size_t)n * C1v + ch] * sc + sh, 0.f);
            atomicMax((int*)&sg[vox * C1v + ch], __float_as_int(val));
        }
        __syncthreads();
        float4* og = (float4*)(out + FEATS_SZ + (size_t)br * 125 * C1v);
        for (int i = tid; i < 125 * C1v / 4; i += 512) og[i] = ((float4*)sg)[i];
    } else {
        int q = blk - BB * RRoi;             // 0..511
        int b = q >> 8;
        int rest = q & 255;
        int n0 = (rest & 63) * 32, o0 = (rest >> 6) * 32;
        int tx = tid & 31, ty = tid >> 5;    // 32 x 16
        #pragma unroll
        for (int r = 0; r < 2; r++) {
            int n_l = ty + r * 16;
            int o = o0 + tx;
            float f = fmaxf(g_h3[(size_t)(b * NN + n0 + n_l) * C1v + o] * ssc[o] + ssh[o], 0.f);
            tt[n_l][tx] = f;
        }
        __syncthreads();
        #pragma unroll
        for (int r = 0; r < 2; r++) {
            int o_l = ty + r * 16;
            out[(size_t)(b * C1v + o0 + o_l) * NN + n0 + tx] = tt[tx][o_l];
        }
    }
}

// ---------------- launch ----------------
extern "C" void kernel_launch(void* const* d_in, const int* in_sizes, int n_in,
                              void* d_out, int out_size) {
    const float* pts    = (const float*)d_in[0];
    const float* feat   = (const float*)d_in[1];
    const float* rois   = (const float*)d_in[2];
    const float* W_mlp  = (const float*)d_in[3];
    const float* g_mlp  = (const float*)d_in[4];
    const float* btm    = (const float*)d_in[5];
    const float* W1     = (const float*)d_in[6];
    const float* b1     = (const float*)d_in[7];
    const float* g1     = (const float*)d_in[8];
    const float* bt1    = (const float*)d_in[9];
    const float* W2     = (const float*)d_in[10];
    const float* b2     = (const float*)d_in[11];
    const float* g2     = (const float*)d_in[12];
    const float* bt2    = (const float*)d_in[13];
    float* out = (float*)d_out;

    cudaFuncSetAttribute(k_final, cudaFuncAttributeMaxDynamicSharedMemorySize,
                         125 * C1v * sizeof(float));

    // fork: frontB (neigh + roi) runs concurrent with frontA -> gemmG
    cudaStream_t s2;
    cudaStreamCreateWithFlags(&s2, cudaStreamNonBlocking);
    cudaEvent_t e0, e1;
    cudaEventCreateWithFlags(&e0, cudaEventDisableTiming);
    cudaEventCreateWithFlags(&e1, cudaEventDisableTiming);

    cudaEventRecord(e0, 0);
    cudaStreamWaitEvent(s2, e0, 0);
    k_frontB<<<768, 256, 0, s2>>>(pts, rois);
    cudaEventRecord(e1, s2);

    k_frontA<<<739, 256>>>(feat, W_mlp, W1, W2);
    k_gemmG<<<dim3(NN / 64, 256 / 32, BB), 128>>>();
    cudaStreamWaitEvent(0, e1, 0);
    k_gathermax<<<dim3(NN / PPB, BB), 256>>>(pts);
    k_conv1<<<BB * NN / 4, 256>>>(g_mlp, btm);
    k_gemm1<<<dim3(NN / 64, C1v / 32, BB), 128>>>(b1);
    k_conv2<<<BB * NN / 8, 256>>>(g1, bt1);
    k_gemm2<<<dim3(NN / 64, C1v / 32, BB), 128>>>(b2);
    k_final<<<BB * RRoi + 512, 512, 125 * C1v * sizeof(float)>>>(g2, bt2, out);
}

// round 15
// speedup vs baseline: 1.3820x; 1.0348x over previous
#include <cuda_runtime.h>
#include <cuda_bf16.h>
#include <math.h>

// Problem constants
#define BB   2
#define NN   2048
#define RRoi 128
#define CINv 256
#define NSv  16
#define C1v  128
#define RADv 0.3f
#define EPSv 1e-5f
#define FEATS_SZ (BB*C1v*NN)          // 524288

// ---------------- scratch ----------------
__device__ int   g_idx[BB*NN*NSv];
__device__ float g_Gt[BB*NN*256];        // [b][n][o]
__device__ float g_hmax[BB*NN*256];      // [b][n][c]
__device__ float g_h2[BB*NN*C1v];        // [b][n][o]
__device__ float g_h3[BB*NN*C1v];        // [b][n][o]
__device__ float g_WxT[3*256];           // [k][o]
__device__ unsigned g_Wfh[256*128], g_Wfl[256*128];
__device__ unsigned g_W1h[128*128], g_W1l[128*128];
__device__ unsigned g_W2h[128*64],  g_W2l[128*64];
__device__ unsigned g_Fh[BB*NN*128],  g_Fl[BB*NN*128];
__device__ unsigned g_A1h[BB*NN*128], g_A1l[BB*NN*128];
__device__ unsigned g_A2h[BB*NN*64],  g_A2l[BB*NN*64];
__device__ int   g_roilst[BB*RRoi*NN];
__device__ int   g_roicnt[BB*RRoi];
__device__ float g_stats[1024];

// ---------------- helpers ----------------
__device__ __forceinline__ unsigned pack_split(float x0, float x1, unsigned& lo) {
    __nv_bfloat16 h0 = __float2bfloat16(x0);
    __nv_bfloat16 h1 = __float2bfloat16(x1);
    __nv_bfloat16 l0 = __float2bfloat16(x0 - __bfloat162float(h0));
    __nv_bfloat16 l1 = __float2bfloat16(x1 - __bfloat162float(h1));
    lo = ((unsigned)__bfloat16_as_ushort(l1) << 16) | (unsigned)__bfloat16_as_ushort(l0);
    return ((unsigned)__bfloat16_as_ushort(h1) << 16) | (unsigned)__bfloat16_as_ushort(h0);
}

__device__ __forceinline__ void mma16816(float* d, const unsigned* a, const unsigned* b) {
    asm volatile(
        "mma.sync.aligned.m16n8k16.row.col.f32.bf16.bf16.f32 "
        "{%0,%1,%2,%3}, {%4,%5,%6,%7}, {%8,%9}, {%0,%1,%2,%3};"
        : "+f"(d[0]), "+f"(d[1]), "+f"(d[2]), "+f"(d[3])
        : "r"(a[0]), "r"(a[1]), "r"(a[2]), "r"(a[3]), "r"(b[0]), "r"(b[1]));
}

struct SmemGemm {
    unsigned wh[2][32][12], wl[2][32][12];
    unsigned ah[2][64][12], al[2][64][12];
    float outT[64][36];
};

// pure-MMA mainloop: 32o x 64n tile, 128 threads (R10-proven)
template<int KSTEPS>
__device__ __forceinline__ void gemm_mainloop(
    SmemGemm& s,
    const unsigned* __restrict__ Wh, const unsigned* __restrict__ Wl,
    const unsigned* __restrict__ Ah, const unsigned* __restrict__ Al,
    int o0, size_t nbase, float (*d)[4], int tid)
{
    const int kw2 = KSTEPS * 8;
    int lane = tid & 31, warp = tid >> 5;
    int g = lane >> 2, t = lane & 3;
    int wn0 = warp * 16;
    int srw = tid >> 1;
    int sq = (tid & 1) * 4;
    if (tid < 64) {
        *(uint4*)&s.wh[0][srw][sq] = *(const uint4*)&Wh[(size_t)(o0 + srw) * kw2 + sq];
        *(uint4*)&s.wl[0][srw][sq] = *(const uint4*)&Wl[(size_t)(o0 + srw) * kw2 + sq];
    }
    *(uint4*)&s.ah[0][srw][sq] = *(const uint4*)&Ah[(nbase + srw) * kw2 + sq];
    *(uint4*)&s.al[0][srw][sq] = *(const uint4*)&Al[(nbase + srw) * kw2 + sq];
    __syncthreads();
    int buf = 0;
    #pragma unroll
    for (int ks = 0; ks < KSTEPS; ks++) {
        uint4 nwh, nwl, nah, nal;
        if (ks + 1 < KSTEPS) {
            int kw = (ks + 1) * 8 + sq;
            if (tid < 64) {
                nwh = *(const uint4*)&Wh[(size_t)(o0 + srw) * kw2 + kw];
                nwl = *(const uint4*)&Wl[(size_t)(o0 + srw) * kw2 + kw];
            }
            nah = *(const uint4*)&Ah[(nbase + srw) * kw2 + kw];
            nal = *(const uint4*)&Al[(nbase + srw) * kw2 + kw];
        }
        unsigned whf[2][4], wlf[2][4], bhf[2][2], blf[2][2];
        #pragma unroll
        for (int j = 0; j < 2; j++) {
            int r0 = j * 16 + g;
            whf[j][0] = s.wh[buf][r0][t];     whf[j][1] = s.wh[buf][r0 + 8][t];
            whf[j][2] = s.wh[buf][r0][t + 4]; whf[j][3] = s.wh[buf][r0 + 8][t + 4];
            wlf[j][0] = s.wl[buf][r0][t];     wlf[j][1] = s.wl[buf][r0 + 8][t];
            wlf[j][2] = s.wl[buf][r0][t + 4]; wlf[j][3] = s.wl[buf][r0 + 8][t + 4];
        }
        #pragma unroll
        for (int i = 0; i < 2; i++) {
            int n = wn0 + i * 8 + g;
            bhf[i][0] = s.ah[buf][n][t]; bhf[i][1] = s.ah[buf][n][t + 4];
            blf[i][0] = s.al[buf][n][t]; blf[i][1] = s.al[buf][n][t + 4];
        }
        #pragma unroll
        for (int j = 0; j < 2; j++)
            #pragma unroll
            for (int i = 0; i < 2; i++) {
                mma16816(d[j * 2 + i], whf[j], bhf[i]);
                mma16816(d[j * 2 + i], whf[j], blf[i]);
                mma16816(d[j * 2 + i], wlf[j], bhf[i]);
            }
        if (ks + 1 < KSTEPS) {
            if (tid < 64) {
                *(uint4*)&s.wh[buf ^ 1][srw][sq] = nwh;
                *(uint4*)&s.wl[buf ^ 1][srw][sq] = nwl;
            }
            *(uint4*)&s.ah[buf ^ 1][srw][sq] = nah;
            *(uint4*)&s.al[buf ^ 1][srw][sq] = nal;
        }
        __syncthreads();
        buf ^= 1;
    }
    #pragma unroll
    for (int j = 0; j < 2; j++)
        #pragma unroll
        for (int i = 0; i < 2; i++) {
            int nc = wn0 + i * 8 + 2 * t;
            s.outT[nc][j * 16 + g]     = d[j * 2 + i][0];
            s.outT[nc + 1][j * 16 + g] = d[j * 2 + i][1];
            s.outT[nc][j * 16 + g + 8]     = d[j * 2 + i][2];
            s.outT[nc + 1][j * 16 + g + 8] = d[j * 2 + i][3];
        }
    __syncthreads();
}

// ---------------- fused front: stats zero + weight splits + feature split-transpose + neigh + roi ----------------
__global__ void k_front(const float* __restrict__ pts, const float* __restrict__ rois,
                        const float* __restrict__ feat,
                        const float* __restrict__ Wm, const float* __restrict__ W1,
                        const float* __restrict__ W2) {
    __shared__ __align__(16) char sbuf[24576];
    int blk = blockIdx.x;
    if (blk < 227) {
        if (blk == 0) {
            for (int i = threadIdx.x; i < 1024; i += 256) g_stats[i] = 0.f;
        }
        int id = blk * 256 + threadIdx.x;          // < 58112
        if (id < 32768) {
            int o = id >> 7, c2 = id & 127;
            unsigned lo;
            unsigned hi = pack_split(Wm[o * 259 + 3 + 2 * c2], Wm[o * 259 + 4 + 2 * c2], lo);
            g_Wfh[id] = hi; g_Wfl[id] = lo;
        } else if (id < 33536) {
            int t2 = id - 32768; int o = t2 & 255, k = t2 >> 8;
            g_WxT[t2] = Wm[o * 259 + k];
        } else if (id < 49920) {
            int t2 = id - 33536; int o = t2 >> 7, c2 = t2 & 127;
            unsigned lo;
            unsigned hi = pack_split(W1[o * 256 + 2 * c2], W1[o * 256 + 2 * c2 + 1], lo);
            g_W1h[t2] = hi; g_W1l[t2] = lo;
        } else if (id < 58112) {
            int t2 = id - 49920; int o = t2 >> 6, c2 = t2 & 63;
            unsigned lo;
            unsigned hi = pack_split(W2[o * 128 + 2 * c2], W2[o * 128 + 2 * c2 + 1], lo);
            g_W2h[t2] = hi; g_W2l[t2] = lo;
        }
    } else if (blk < 739) {
        // neighbor search: warp-per-point ballot scan
        int q = blk - 227;
        int b = q >> 8, chunk = q & 255;
        float* sx = (float*)sbuf;
        float* sy = sx + NN;
        float* sz = sx + 2 * NN;
        const float* P = pts + (size_t)b * NN * 3;
        for (int j = threadIdx.x; j < NN; j += 256) {
            sx[j] = P[j * 3 + 0]; sy[j] = P[j * 3 + 1]; sz[j] = P[j * 3 + 2];
        }
        __syncthreads();
        int warp = threadIdx.x >> 5, lane = threadIdx.x & 31;
        int i = chunk * 8 + warp;
        float xi = sx[i], yi = sy[i], zi = sz[i];
        int base = (b * NN + i) * NSv;
        const float r2 = RADv * RADv;
        int cnt = 0, f0 = -1;
        for (int j0 = 0; j0 < NN; j0 += 32) {
            int j = j0 + lane;
            float dx = sx[j] - xi, dy = sy[j] - yi, dz = sz[j] - zi;
            bool qq = (dx * dx + dy * dy + dz * dz) < r2;
            unsigned m = __ballot_sync(0xffffffffu, qq);
            if (m) {
                if (f0 < 0) f0 = j0 + __ffs(m) - 1;
                int pos = cnt + __popc(m & ((1u << lane) - 1u));
                if (qq && pos < NSv) g_idx[base + pos] = j;
                cnt += __popc(m);
                if (cnt >= NSv) break;
            }
        }
        if (cnt < NSv) {
            for (int s = cnt + lane; s < NSv; s += 32) g_idx[base + s] = f0;
        }
    } else if (blk < 995) {
        // roi point-in-box classify
        int br = blk - 739;
        int b = br >> 7;
        int* cnt = (int*)sbuf;
        if (threadIdx.x == 0) *cnt = 0;
        __syncthreads();
        const float* qr = rois + (size_t)br * 7;
        float cx = qr[0], cy = qr[1], cz = qr[2];
        float hx = qr[3] * 0.5f, hy = qr[4] * 0.5f, hz = qr[5] * 0.5f;
        float co = cosf(qr[6]), si = sinf(qr[6]);
        const float* P = pts + (size_t)b * NN * 3;
        int* lst = g_roilst + (size_t)br * NN;
        for (int n = threadIdx.x; n < NN; n += 256) {
            float rx = P[n * 3 + 0] - cx;
            float ry = P[n * 3 + 1] - cy;
            float rz = P[n * 3 + 2] - cz;
            float lx = rx * co + ry * si;
            float ly = -rx * si + ry * co;
            float lz = rz;
            if (fabsf(lx) < hx && fabsf(ly) < hy && fabsf(lz) < hz) {
                int v0 = (int)fminf(fmaxf(floorf((lx + hx) / (2.f * hx) * 5.f), 0.f), 4.f);
                int v1 = (int)fminf(fmaxf(floorf((ly + hy) / (2.f * hy) * 5.f), 0.f), 4.f);
                int v2 = (int)fminf(fmaxf(floorf((lz + hz) / (2.f * hz) * 5.f), 0.f), 4.f);
                int vox = (v0 * 5 + v1) * 5 + v2;
                int pos = atomicAdd(cnt, 1);
                lst[pos] = (vox << 12) | n;
            }
        }
        __syncthreads();
        if (threadIdx.x == 0) g_roicnt[br] = *cnt;
    } else {
        // feature split-transpose: feat[b][c][n] fp32 -> g_Fh/Fl [b][n][c/2]
        int q2 = blk - 995;                 // 0..511
        int b = q2 >> 8;
        int rest = q2 & 255;
        int c0 = (rest >> 6) * 64;
        int n0 = (rest & 63) * 32;
        float* tile = (float*)sbuf;         // [64][33]
        int tx = threadIdx.x & 31, ty = threadIdx.x >> 5;
        #pragma unroll
        for (int r8 = 0; r8 < 8; r8++) {
            int row = r8 * 8 + ty;
            tile[row * 33 + tx] = feat[(size_t)(b * 256 + c0 + row) * NN + n0 + tx];
        }
        __syncthreads();
        int n_l = threadIdx.x >> 3;
        int c2_l = threadIdx.x & 7;
        #pragma unroll
        for (int q = 0; q < 4; q++) {
            int c2 = q * 8 + c2_l;
            unsigned lo;
            unsigned hi = pack_split(tile[(2 * c2) * 33 + n_l], tile[(2 * c2 + 1) * 33 + n_l], lo);
            size_t off = (size_t)(b * NN + n0 + n_l) * 128 + c0 / 2 + c2;
            g_Fh[off] = hi; g_Fl[off] = lo;
        }
    }
}

// ---------------- GEMM G: Gt[b][n][o] = Wf @ feat, pure MMA ----------------
__global__ void k_gemmG() {
    __shared__ SmemGemm s;
    int b = blockIdx.z;
    int n0 = blockIdx.x * 64, o0 = blockIdx.y * 32;
    int tid = threadIdx.x;
    float d[4][4] = {};
    gemm_mainloop<16>(s, g_Wfh, g_Wfl, g_Fh, g_Fl, o0, (size_t)(b * NN + n0), d, tid);
    int n_l = tid >> 1, q = tid & 1;
    float* orow = &g_Gt[(size_t)(b * NN + n0 + n_l) * 256 + o0 + q * 16];
    #pragma unroll
    for (int f = 0; f < 4; f++)
        *(float4*)&orow[f * 4] = *(float4*)&s.outT[n_l][q * 16 + f * 4];
}

// ---------------- gathermax: interleaved dual-point chains for 2x MLP ----------------
#define PPB 8
__global__ void k_gathermax(const float* __restrict__ pts) {
    __shared__ int   sj[PPB * NSv];
    __shared__ float srx[PPB * NSv], sry[PPB * NSv], srz[PPB * NSv];
    __shared__ float ssum[4][256], ssq[4][256];
    int b = blockIdx.y;
    int n0 = blockIdx.x * PPB;
    int tid = threadIdx.x;
    if (tid < PPB * NSv) {
        int p = tid >> 4, sI = tid & 15;
        int n = n0 + p;
        int j = g_idx[(b * NN + n) * NSv + sI];
        sj[tid] = j;
        const float* P = pts + (size_t)b * NN * 3;
        srx[tid] = (P[j * 3 + 0] - P[n * 3 + 0]) / RADv;
        sry[tid] = (P[j * 3 + 1] - P[n * 3 + 1]) / RADv;
        srz[tid] = (P[j * 3 + 2] - P[n * 3 + 2]) / RADv;
    }
    __syncthreads();
    int co = tid & 63;
    int pg = tid >> 6;
    float4 w0 = *(const float4*)&g_WxT[co * 4];
    float4 w1 = *(const float4*)&g_WxT[256 + co * 4];
    float4 w2 = *(const float4*)&g_WxT[512 + co * 4];
    float4 ls = make_float4(0.f, 0.f, 0.f, 0.f);
    float4 lq = make_float4(0.f, 0.f, 0.f, 0.f);
    const float* Gb = g_Gt + (size_t)b * NN * 256;
    int pA = pg * 2, pB = pg * 2 + 1;
    float4 mA = make_float4(-3.4e38f, -3.4e38f, -3.4e38f, -3.4e38f);
    float4 mB = mA;
    #pragma unroll
    for (int sI = 0; sI < NSv; sI++) {
        int eA = pA * NSv + sI, eB = pB * NSv + sI;
        int jA = sj[eA], jB = sj[eB];
        float4 gvA = *(const float4*)&Gb[(size_t)jA * 256 + co * 4];
        float4 gvB = *(const float4*)&Gb[(size_t)jB * 256 + co * 4];
        float rxA = srx[eA], ryA = sry[eA], rzA = srz[eA];
        float rxB = srx[eB], ryB = sry[eB], rzB = srz[eB];
        float4 vA, vB;
        vA.x = gvA.x + w0.x * rxA + w1.x * ryA + w2.x * rzA;
        vA.y = gvA.y + w0.y * rxA + w1.y * ryA + w2.y * rzA;
        vA.z = gvA.z + w0.z * rxA + w1.z * ryA + w2.z * rzA;
        vA.w = gvA.w + w0.w * rxA + w1.w * ryA + w2.w * rzA;
        vB.x = gvB.x + w0.x * rxB + w1.x * ryB + w2.x * rzB;
        vB.y = gvB.y + w0.y * rxB + w1.y * ryB + w2.y * rzB;
        vB.z = gvB.z + w0.z * rxB + w1.z * ryB + w2.z * rzB;
        vB.w = gvB.w + w0.w * rxB + w1.w * ryB + w2.w * rzB;
        mA.x = fmaxf(mA.x, vA.x); mA.y = fmaxf(mA.y, vA.y);
        mA.z = fmaxf(mA.z, vA.z); mA.w = fmaxf(mA.w, vA.w);
        mB.x = fmaxf(mB.x, vB.x); mB.y = fmaxf(mB.y, vB.y);
        mB.z = fmaxf(mB.z, vB.z); mB.w = fmaxf(mB.w, vB.w);
        ls.x += vA.x + vB.x; ls.y += vA.y + vB.y;
        ls.z += vA.z + vB.z; ls.w += vA.w + vB.w;
        lq.x += vA.x * vA.x + vB.x * vB.x; lq.y += vA.y * vA.y + vB.y * vB.y;
        lq.z += vA.z * vA.z + vB.z * vB.z; lq.w += vA.w * vA.w + vB.w * vB.w;
    }
    *(float4*)&g_hmax[(size_t)(b * NN + n0 + pA) * 256 + co * 4] = mA;
    *(float4*)&g_hmax[(size_t)(b * NN + n0 + pB) * 256 + co * 4] = mB;
    ssum[pg][co * 4 + 0] = ls.x; ssum[pg][co * 4 + 1] = ls.y;
    ssum[pg][co * 4 + 2] = ls.z; ssum[pg][co * 4 + 3] = ls.w;
    ssq[pg][co * 4 + 0] = lq.x; ssq[pg][co * 4 + 1] = lq.y;
    ssq[pg][co * 4 + 2] = lq.z; ssq[pg][co * 4 + 3] = lq.w;
    __syncthreads();
    float ts = ssum[0][tid] + ssum[1][tid] + ssum[2][tid] + ssum[3][tid];
    float tq = ssq[0][tid] + ssq[1][tid] + ssq[2][tid] + ssq[3][tid];
    atomicAdd(&g_stats[tid], ts);
    atomicAdd(&g_stats[256 + tid], tq);
}

// ---------------- conv1: relu(bn1(hmax)) -> split bf16, 1 row/thread, grid 1024 (R9-best) ----------------
__global__ void k_conv1(const float* __restrict__ gm, const float* __restrict__ btm) {
    __shared__ float ssc[256], ssh[256];
    int tid = threadIdx.x;
    {
        float m = g_stats[tid] * (1.f / 65536.f);
        float v = g_stats[256 + tid] * (1.f / 65536.f) - m * m;
        float sc = gm[tid] * rsqrtf(v + EPSv);
        ssc[tid] = sc; ssh[tid] = btm[tid] - m * sc;
    }
    __syncthreads();
    int bn = blockIdx.x * 4 + (tid >> 6);
    int c4 = (tid & 63) * 4;
    float4 v = *(const float4*)&g_hmax[(size_t)bn * 256 + c4];
    float x0 = fmaxf(v.x * ssc[c4] + ssh[c4], 0.f);
    float x1 = fmaxf(v.y * ssc[c4 + 1] + ssh[c4 + 1], 0.f);
    float x2 = fmaxf(v.z * ssc[c4 + 2] + ssh[c4 + 2], 0.f);
    float x3 = fmaxf(v.w * ssc[c4 + 3] + ssh[c4 + 3], 0.f);
    unsigned lo0, lo1;
    unsigned hi0 = pack_split(x0, x1, lo0);
    unsigned hi1 = pack_split(x2, x3, lo1);
    *(uint2*)&g_A1h[(size_t)bn * 128 + c4 / 2] = make_uint2(hi0, hi1);
    *(uint2*)&g_A1l[(size_t)bn * 128 + c4 / 2] = make_uint2(lo0, lo1);
}

// ---------------- GEMM1: h2[b][n][o] = b1 + W1 @ A1, fused BN2 stats ----------------
__global__ void k_gemm1(const float* __restrict__ b1) {
    __shared__ SmemGemm s;
    int b = blockIdx.z;
    int n0 = blockIdx.x * 64, o0 = blockIdx.y * 32;
    int tid = threadIdx.x;
    float d[4][4] = {};
    gemm_mainloop<16>(s, g_W1h, g_W1l, g_A1h, g_A1l, o0, (size_t)(b * NN + n0), d, tid);
    int o_l = tid & 31, chunk = tid >> 5;
    int o = o0 + o_l;
    float bias = b1[o];
    float sum = 0.f, sq = 0.f;
    #pragma unroll
    for (int r = 0; r < 16; r++) {
        int n = chunk * 16 + r;
        float v = s.outT[n][o_l] + bias;
        sum += v; sq += v * v;
        g_h2[(size_t)(b * NN + n0 + n) * C1v + o] = v;
    }
    atomicAdd(&g_stats[512 + o], sum);
    atomicAdd(&g_stats[640 + o], sq);
}

// ---------------- conv2: relu(bn2(h2)) -> split bf16, 1 row/thread, grid 512 (R9-best) ----------------
__global__ void k_conv2(const float* __restrict__ g1, const float* __restrict__ bt1) {
    __shared__ float ssc[128], ssh[128];
    int tid = threadIdx.x;
    if (tid < 128) {
        float m = g_stats[512 + tid] * (1.f / 4096.f);
        float v = g_stats[640 + tid] * (1.f / 4096.f) - m * m;
        float sc = g1[tid] * rsqrtf(v + EPSv);
        ssc[tid] = sc; ssh[tid] = bt1[tid] - m * sc;
    }
    __syncthreads();
    int bn = blockIdx.x * 8 + (tid >> 5);
    int c4 = (tid & 31) * 4;
    float4 v = *(const float4*)&g_h2[(size_t)bn * 128 + c4];
    float x0 = fmaxf(v.x * ssc[c4] + ssh[c4], 0.f);
    float x1 = fmaxf(v.y * ssc[c4 + 1] + ssh[c4 + 1], 0.f);
    float x2 = fmaxf(v.z * ssc[c4 + 2] + ssh[c4 + 2], 0.f);
    float x3 = fmaxf(v.w * ssc[c4 + 3] + ssh[c4 + 3], 0.f);
    unsigned lo0, lo1;
    unsigned hi0 = pack_split(x0, x1, lo0);
    unsigned hi1 = pack_split(x2, x3, lo1);
    *(uint2*)&g_A2h[(size_t)bn * 64 + c4 / 2] = make_uint2(hi0, hi1);
    *(uint2*)&g_A2l[(size_t)bn * 64 + c4 / 2] = make_uint2(lo0, lo1);
}

// ---------------- GEMM2: h3[b][n][o] = b2 + W2 @ A2, fused BN3 stats ----------------
__global__ void k_gemm2(const float* __restrict__ b2) {
    __shared__ SmemGemm s;
    int b = blockIdx.z;
    int n0 = blockIdx.x * 64, o0 = blockIdx.y * 32;
    int tid = threadIdx.x;
    float d[4][4] = {};
    gemm_mainloop<8>(s, g_W2h, g_W2l, g_A2h, g_A2l, o0, (size_t)(b * NN + n0), d, tid);
    int o_l = tid & 31, chunk = tid >> 5;
    int o = o0 + o_l;
    float bias = b2[o];
    float sum = 0.f, sq = 0.f;
    #pragma unroll
    for (int r = 0; r < 16; r++) {
        int n = chunk * 16 + r;
        float v = s.outT[n][o_l] + bias;
        sum += v; sq += v * v;
        g_h3[(size_t)(b * NN + n0 + n) * C1v + o] = v;
    }
    atomicAdd(&g_stats[768 + o], sum);
    atomicAdd(&g_stats[896 + o], sq);
}

// ---------------- final: roipool (inline BN3 from h3) + feats output, merged ----------------
__global__ void k_final(const float* __restrict__ g2, const float* __restrict__ bt2,
                        float* __restrict__ out) {
    extern __shared__ float sg[];            // 125*128 floats (roipool blocks)
    __shared__ float ssc[128], ssh[128];
    __shared__ float tt[32][33];
    int blk = blockIdx.x;
    int tid = threadIdx.x;                   // 512
    if (tid < 128) {
        float m = g_stats[768 + tid] * (1.f / 4096.f);
        float v = g_stats[896 + tid] * (1.f / 4096.f) - m * m;
        float sc = g2[tid] * rsqrtf(v + EPSv);
        ssc[tid] = sc; ssh[tid] = bt2[tid] - m * sc;
    }
    __syncthreads();
    if (blk < BB * RRoi) {
        int br = blk;
        int b = br >> 7;
        for (int i = tid; i < 125 * C1v / 4; i += 512)
            ((float4*)sg)[i] = make_float4(0.f, 0.f, 0.f, 0.f);
        __syncthreads();
        const float* H = g_h3 + (size_t)b * NN * C1v;
        const int* lst = g_roilst + (size_t)br * NN;
        int m = g_roicnt[br];
        int ch = tid & 127;
        int slot = tid >> 7;
        float sc = ssc[ch], sh = ssh[ch];
        for (int e = slot; e < m; e += 4) {
            int pk = lst[e];
            int n = pk & 4095;
            int vox = pk >> 12;
            float val = fmaxf(H[(size_t)n * C1v + ch] * sc + sh, 0.f);
            atomicMax((int*)&sg[vox * C1v + ch], __float_as_int(val));
        }
        __syncthreads();
        float4* og = (float4*)(out + FEATS_SZ + (size_t)br * 125 * C1v);
        for (int i = tid; i < 125 * C1v / 4; i += 512) og[i] = ((float4*)sg)[i];
    } else {
        int q = blk - BB * RRoi;             // 0..511
        int b = q >> 8;
        int rest = q & 255;
        int n0 = (rest & 63) * 32, o0 = (rest >> 6) * 32;
        int tx = tid & 31, ty = tid >> 5;    // 32 x 16
        #pragma unroll
        for (int r = 0; r < 2; r++) {
            int n_l = ty + r * 16;
            int o = o0 + tx;
            float f = fmaxf(g_h3[(size_t)(b * NN + n0 + n_l) * C1v + o] * ssc[o] + ssh[o], 0.f);
            tt[n_l][tx] = f;
        }
        __syncthreads();
        #pragma unroll
        for (int r = 0; r < 2; r++) {
            int o_l = ty + r * 16;
            out[(size_t)(b * C1v + o0 + o_l) * NN + n0 + tx] = tt[tx][o_l];
        }
    }
}

// ---------------- launch ----------------
extern "C" void kernel_launch(void* const* d_in, const int* in_sizes, int n_in,
                              void* d_out, int out_size) {
    const float* pts    = (const float*)d_in[0];
    const float* feat   = (const float*)d_in[1];
    const float* rois   = (const float*)d_in[2];
    const float* W_mlp  = (const float*)d_in[3];
    const float* g_mlp  = (const float*)d_in[4];
    const float* btm    = (const float*)d_in[5];
    const float* W1     = (const float*)d_in[6];
    const float* b1     = (const float*)d_in[7];
    const float* g1     = (const float*)d_in[8];
    const float* bt1    = (const float*)d_in[9];
    const float* W2     = (const float*)d_in[10];
    const float* b2     = (const float*)d_in[11];
    const float* g2     = (const float*)d_in[12];
    const float* bt2    = (const float*)d_in[13];
    float* out = (float*)d_out;

    cudaFuncSetAttribute(k_final, cudaFuncAttributeMaxDynamicSharedMemorySize,
                         125 * C1v * sizeof(float));

    k_front<<<1507, 256>>>(pts, rois, feat, W_mlp, W1, W2);
    k_gemmG<<<dim3(NN / 64, 256 / 32, BB), 128>>>();
    k_gathermax<<<dim3(NN / PPB, BB), 256>>>(pts);
    k_conv1<<<BB * NN / 4, 256>>>(g_mlp, btm);
    k_gemm1<<<dim3(NN / 64, C1v / 32, BB), 128>>>(b1);
    k_conv2<<<BB * NN / 8, 256>>>(g1, bt1);
    k_gemm2<<<dim3(NN / 64, C1v / 32, BB), 128>>>(b2);
    k_final<<<BB * RRoi + 512, 512, 125 * C1v * sizeof(float)>>>(g2, bt2, out);
}